// round 16
// baseline (speedup 1.0000x reference)
#include <cuda_runtime.h>
#include <cuda_fp16.h>
#include <math.h>
#include <stdint.h>

// ---------------- problem constants ----------------
#define ROWS      40960
#define CDIM      192
#define NWIN      320
#define BH        768
#define MLPH      768
#define QK_SCALE  0.17677669529663687f

// ---------------- scratch ----------------
__device__ float g_h [ (size_t)ROWS * CDIM ];
__device__ __half g_qh[ (size_t)BH * NWIN * 32 ];
__device__ __half g_kh[ (size_t)BH * NWIN * 32 ];
__device__ __half g_vh[ (size_t)BH * NWIN * 32 ];
__device__ float g_a [ (size_t)ROWS * CDIM ];
__device__ float g_x1[ (size_t)ROWS * CDIM ];
__device__ float g_g [ (size_t)ROWS * MLPH ];
__device__ float g_bias6[ 6 * NWIN * NWIN ];
// fp16 weights
__device__ __half g_wq[576 * 192];
__device__ __half g_wp[192 * 192];
__device__ __half g_w1[768 * 192];
__device__ __half g_w2[192 * 768];

__device__ __forceinline__ int winmap(int wr) {
    int b_ = wr / NWIN, n = wr - b_ * NWIN;
    int b  = b_ >> 6,  w = b_ & 63;
    int wh = w >> 3,   ww = w & 7;
    int t  = n >> 6;
    int rem = n & 63;
    int i = rem >> 3, j = rem & 7;
    int hs = (wh * 8 + i + 4) & 63;
    int ws = (ww * 8 + j + 4) & 63;
    return ((b * 5 + t) << 12) + (hs << 6) + ws;
}

// ---------------- mma helpers ----------------
__device__ __forceinline__ uint32_t smem_u32(const void* p) {
    uint32_t a;
    asm("{ .reg .u64 t; cvta.to.shared.u64 t, %1; cvt.u32.u64 %0, t; }" : "=r"(a) : "l"(p));
    return a;
}
__device__ __forceinline__ void ldsm4(uint32_t* r, uint32_t a) {
    asm volatile("ldmatrix.sync.aligned.m8n8.x4.shared.b16 {%0,%1,%2,%3}, [%4];"
        : "=r"(r[0]), "=r"(r[1]), "=r"(r[2]), "=r"(r[3]) : "r"(a));
}
__device__ __forceinline__ void ldsm2(uint32_t* r, uint32_t a) {
    asm volatile("ldmatrix.sync.aligned.m8n8.x2.shared.b16 {%0,%1}, [%2];"
        : "=r"(r[0]), "=r"(r[1]) : "r"(a));
}
__device__ __forceinline__ void mma16816(float* c, const uint32_t* a, const uint32_t* b) {
    asm volatile("mma.sync.aligned.m16n8k16.row.col.f32.f16.f16.f32 "
        "{%0,%1,%2,%3}, {%4,%5,%6,%7}, {%8,%9}, {%0,%1,%2,%3};"
        : "+f"(c[0]), "+f"(c[1]), "+f"(c[2]), "+f"(c[3])
        : "r"(a[0]), "r"(a[1]), "r"(a[2]), "r"(a[3]), "r"(b[0]), "r"(b[1]));
}

// ---------------- merged weight fp16 conversion ----------------
#define NWQ (576*192)
#define NWP (192*192)
#define NW1 (768*192)
#define NW2 (192*768)
__global__ void cvt_all(const float* __restrict__ qkvw, const float* __restrict__ projw,
                        const float* __restrict__ f1w, const float* __restrict__ f2w) {
    int i = blockIdx.x * 256 + threadIdx.x;
    if (i < NWQ) g_wq[i] = __float2half(qkvw[i]);
    else if (i < NWQ + NWP) g_wp[i - NWQ] = __float2half(projw[i - NWQ]);
    else if (i < NWQ + NWP + NW1) g_w1[i - NWQ - NWP] = __float2half(f1w[i - NWQ - NWP]);
    else if (i < NWQ + NWP + NW1 + NW2) g_w2[i - NWQ - NWP - NW1] = __float2half(f2w[i - NWQ - NWP - NW1]);
}

// ---------------- relative-position bias precompute ----------------
__global__ void bias_kernel(const float* __restrict__ table) {
    int e = blockIdx.x * 1024 + threadIdx.x;
    if (e >= 6 * NWIN * NWIN) return;
    int head = e / (NWIN * NWIN);
    int r = e - head * (NWIN * NWIN);
    int n = r / NWIN, m = r - n * NWIN;
    int t1 = n >> 6, p1 = n & 63, i1 = p1 >> 3, j1 = p1 & 7;
    int t2 = m >> 6, p2 = m & 63, i2 = p2 >> 3, j2 = p2 & 7;
    int idx = (t1 - t2 + 7) * 15 + (i1 - i2 + 7) + (j1 - j2);
    g_bias6[e] = table[idx * 6 + head];
}

// ---------------- LayerNorm ----------------
template<int SRC>
__global__ __launch_bounds__(256) void ln_kernel(const float* __restrict__ in,
                                                 const float* __restrict__ gw,
                                                 const float* __restrict__ bw) {
    int row  = blockIdx.x * 8 + (threadIdx.x >> 5);
    int lane = threadIdx.x & 31;
    const float* src = (SRC == 0) ? in : g_x1;
    const float* p = src + (size_t)row * CDIM;
    float v[6];
    float s = 0.f;
#pragma unroll
    for (int u = 0; u < 6; u++) { v[u] = p[lane + 32 * u]; s += v[u]; }
#pragma unroll
    for (int o = 16; o; o >>= 1) s += __shfl_xor_sync(0xffffffffu, s, o);
    float mu = s * (1.0f / CDIM);
    float q = 0.f;
#pragma unroll
    for (int u = 0; u < 6; u++) { float d = v[u] - mu; q += d * d; }
#pragma unroll
    for (int o = 16; o; o >>= 1) q += __shfl_xor_sync(0xffffffffu, q, o);
    float rs = rsqrtf(q * (1.0f / CDIM) + 1e-5f);
    float* o = g_h + (size_t)row * CDIM;
#pragma unroll
    for (int u = 0; u < 6; u++) {
        int c = lane + 32 * u;
        o[c] = (v[u] - mu) * rs * gw[c] + bw[c];
    }
}

// ---------------- GEMM epilogues ----------------
struct EpiQKV {
    __device__ void operator()(int wr, int oc, float val) const {
        int which = oc / CDIM;
        int rem = oc - which * CDIM;
        int h = rem >> 5, d = rem & 31;
        int b_ = wr / NWIN, n = wr - b_ * NWIN;
        size_t off = ((size_t)(b_ * 6 + h)) * (NWIN * 32) + (size_t)n * 32 + d;
        if (which == 0)      g_qh[off] = __float2half(val * QK_SCALE);
        else if (which == 1) g_kh[off] = __float2half(val);
        else                 g_vh[off] = __float2half(val);
    }
};
struct EpiProj {
    const float* x;
    __device__ void operator()(int wr, int c, float v) const {
        int dst = winmap(wr);
        size_t o = (size_t)dst * CDIM + c;
        g_x1[o] = x[o] + v;
    }
};
struct EpiGelu {
    __device__ void operator()(int r, int c, float v) const {
        g_g[(size_t)r * MLPH + c] = 0.5f * v * (1.0f + erff(v * 0.7071067811865476f));
    }
};
struct EpiOut {
    float* out;
    __device__ void operator()(int r, int c, float v) const {
        size_t o = (size_t)r * CDIM + c;
        out[o] = g_x1[o] + v;
    }
};

// ---------------- HMMA GEMM: 128(M) x 64(N) per CTA, K chunks of 64 ----------
template<int ASRC, int WSRC, bool GATHER, class Epi>
__global__ __launch_bounds__(256) void hgemm(const float* __restrict__ bias, int K, Epi epi) {
    __shared__ __align__(128) __half sA[128 * 64];
    __shared__ __align__(128) __half sW[64 * 64];
    const float* Asrc = (ASRC == 1) ? g_h : (ASRC == 2) ? g_a : g_g;
    const __half* Wb = (WSRC == 0) ? g_wq : (WSRC == 1) ? g_wp : (WSRC == 2) ? g_w1 : g_w2;

    int tid = threadIdx.x, lane = tid & 31, warp = tid >> 5;
    int bm = blockIdx.y, bn = blockIdx.x;
    int wm = (warp & 3) * 32, wn = (warp >> 2) * 32;
    uint32_t sAb = smem_u32(sA), sWb = smem_u32(sW);

    int lrow = tid >> 3;
    int kq   = (tid & 7) * 8;
    int cb   = (kq * 2) ^ ((lrow & 7) << 4);

    const float* Aptr[4];
#pragma unroll
    for (int i = 0; i < 4; i++) {
        int grow = bm * 128 + lrow + i * 32;
        int as = GATHER ? winmap(grow) : grow;
        Aptr[i] = Asrc + (size_t)as * K + kq;
    }
    const __half* Wptr[2];
#pragma unroll
    for (int i = 0; i < 2; i++)
        Wptr[i] = Wb + (size_t)(bn * 64 + lrow + i * 32) * K + kq;

    int aq = lane >> 3, ar = lane & 7;
    int a_row0 = wm + ar + (aq & 1) * 8;
    int a_cbase = (aq >> 1) * 16;
    int bl = lane & 15;
    int b_row0 = wn + (bl & 7);
    int b_cbase = ((bl >> 3) & 1) * 16;

    float acc[2][4][4];
#pragma unroll
    for (int mt = 0; mt < 2; mt++)
#pragma unroll
        for (int nt = 0; nt < 4; nt++)
#pragma unroll
            for (int e = 0; e < 4; e++) acc[mt][nt][e] = 0.f;

    int nch = K >> 6;
    for (int ch = 0; ch < nch; ch++) {
        __syncthreads();
        int k0 = ch * 64;
#pragma unroll
        for (int i = 0; i < 4; i++) {
            float4 f0 = *(const float4*)(Aptr[i] + k0);
            float4 f1 = *(const float4*)(Aptr[i] + k0 + 4);
            __half2 h0 = __floats2half2_rn(f0.x, f0.y);
            __half2 h1 = __floats2half2_rn(f0.z, f0.w);
            __half2 h2 = __floats2half2_rn(f1.x, f1.y);
            __half2 h3 = __floats2half2_rn(f1.z, f1.w);
            uint4 u;
            u.x = *(uint32_t*)&h0; u.y = *(uint32_t*)&h1;
            u.z = *(uint32_t*)&h2; u.w = *(uint32_t*)&h3;
            *(uint4*)((char*)sA + (lrow + i * 32) * 128 + cb) = u;
        }
#pragma unroll
        for (int i = 0; i < 2; i++) {
            uint4 v = *(const uint4*)(Wptr[i] + k0);
            *(uint4*)((char*)sW + (lrow + i * 32) * 128 + cb) = v;
        }
        __syncthreads();

#pragma unroll
        for (int ks = 0; ks < 4; ks++) {
            int kb = ks * 32;
            uint32_t afr[2][4];
#pragma unroll
            for (int mt = 0; mt < 2; mt++) {
                int row = a_row0 + mt * 16;
                int c2 = (kb + a_cbase) ^ ((row & 7) << 4);
                ldsm4(afr[mt], sAb + row * 128 + c2);
            }
            uint32_t bfr[4][2];
#pragma unroll
            for (int nt = 0; nt < 4; nt++) {
                int row = b_row0 + nt * 8;
                int c2 = (kb + b_cbase) ^ ((row & 7) << 4);
                ldsm2(bfr[nt], sWb + row * 128 + c2);
            }
#pragma unroll
            for (int mt = 0; mt < 2; mt++)
#pragma unroll
                for (int nt = 0; nt < 4; nt++)
                    mma16816(acc[mt][nt], afr[mt], bfr[nt]);
        }
    }

    int g = lane >> 2, cp = (lane & 3) * 2;
#pragma unroll
    for (int mt = 0; mt < 2; mt++) {
        int r0 = bm * 128 + wm + mt * 16 + g;
#pragma unroll
        for (int nt = 0; nt < 4; nt++) {
            int c0 = bn * 64 + wn + nt * 8 + cp;
            float b0 = bias[c0], b1 = bias[c0 + 1];
            epi(r0,     c0,     acc[mt][nt][0] + b0);
            epi(r0,     c0 + 1, acc[mt][nt][1] + b1);
            epi(r0 + 8, c0,     acc[mt][nt][2] + b0);
            epi(r0 + 8, c0 + 1, acc[mt][nt][3] + b1);
        }
    }
}

// ---------------- HMMA flash attention ----------------
// grid (5, 768), 128 threads (4 warps); warp w owns q rows [rtile*64+w*16, +16).
__global__ __launch_bounds__(128) void attn_kernel() {
    __shared__ __half qs[64 * 40];   // [row][d] rows 80B
    __shared__ __half ks[64 * 40];   // [key][d] (current chunk)
    __shared__ __half vT[32 * 72];   // [d][key] rows 144B
    __shared__ int    lab[64];

    int rtile = blockIdx.x, bh = blockIdx.y;
    int b_ = bh / 6, head = bh - b_ * 6;
    int tid = threadIdx.x, lane = tid & 31, warp = tid >> 5;
    int row6 = tid & 63, dhh = tid >> 6;   // global-load geometry

    {   // Q load (fp16, coalesced)
        const __half* qg = g_qh + ((size_t)bh * NWIN + rtile * 64 + row6) * 32 + dhh * 16;
        uint4 q0 = *(const uint4*)qg;
        uint4 q1 = *(const uint4*)(qg + 8);
        *(uint4*)((char*)qs + row6 * 80 + dhh * 32) = q0;
        *(uint4*)((char*)qs + row6 * 80 + dhh * 32 + 16) = q1;
    }
    if (tid < 64) {
        int w = b_ & 63;
        int wh = w >> 3, ww = w & 7;
        int i = tid >> 3, j = tid & 7;
        int hh = wh * 8 + i, wg = ww * 8 + j;
        int lh = hh < 56 ? 0 : (hh < 60 ? 1 : 2);
        int lw = wg < 56 ? 0 : (wg < 60 ? 1 : 2);
        lab[tid] = lh * 3 + lw;
    }
    const __half* kg = g_kh + ((size_t)bh * NWIN + row6) * 32 + dhh * 16;
    const __half* vg = g_vh + ((size_t)bh * NWIN + row6) * 32 + dhh * 16;
    uint4 ka0 = *(const uint4*)kg, ka1 = *(const uint4*)(kg + 8);
    uint4 va0 = *(const uint4*)vg, va1 = *(const uint4*)(vg + 8);

    __syncthreads();

    int wm = warp * 16, g = lane >> 2, qp = (lane & 3) * 2;
    uint32_t qa[2][4];
    {
        int ar = lane & 7, aq = lane >> 3;
        uint32_t base = smem_u32(qs) + (uint32_t)((wm + ar + (aq & 1) * 8) * 80 + (aq >> 1) * 16);
        ldsm4(qa[0], base);        // d 0..15
        ldsm4(qa[1], base + 32);   // d 16..31
    }
    // per-row mask bitmaps over 64 window-local keys
    int labr0 = lab[wm + g], labr1 = lab[wm + g + 8];
    uint64_t m0 = 0, m1 = 0;
    for (int k2 = 0; k2 < 64; k2++) {
        int lk = lab[k2];
        m0 |= (uint64_t)(lk != labr0) << k2;
        m1 |= (uint64_t)(lk != labr1) << k2;
    }

    float mi0 = -1e30f, mi1 = -1e30f, li0 = 0.f, li1 = 0.f;
    float o[4][4] = {};
    const float* bpr0 = g_bias6 + (size_t)head * (NWIN * NWIN) + (size_t)(rtile * 64 + wm + g) * NWIN;
    const float* bpr1 = bpr0 + 8 * NWIN;
    uint32_t ksb = smem_u32(ks);
    int bl = lane & 15;

    for (int c = 0; c < 5; c++) {
        __syncthreads();
        // store K chunk [key][d]
        *(uint4*)((char*)ks + row6 * 80 + dhh * 32) = ka0;
        *(uint4*)((char*)ks + row6 * 80 + dhh * 32 + 16) = ka1;
        // store V chunk transposed -> vT[d][key]
        {
            __half vh[16];
            *(uint4*)&vh[0] = va0; *(uint4*)&vh[8] = va1;
#pragma unroll
            for (int j = 0; j < 16; j++)
                vT[(dhh * 16 + j) * 72 + row6] = vh[j];
        }
        if (c < 4) {
            kg += 64 * 32; vg += 64 * 32;
            ka0 = *(const uint4*)kg; ka1 = *(const uint4*)(kg + 8);
            va0 = *(const uint4*)vg; va1 = *(const uint4*)(vg + 8);
        }
        __syncthreads();

        // S = Q K^T  (16x64 per warp)
        float s[8][4];
#pragma unroll
        for (int nt = 0; nt < 8; nt++) {
            s[nt][0] = s[nt][1] = s[nt][2] = s[nt][3] = 0.f;
            uint32_t kaddr = ksb + (uint32_t)((nt * 8 + (bl & 7)) * 80 + ((bl >> 3) & 1) * 16);
            uint32_t kb[2], kb2[2];
            ldsm2(kb,  kaddr);        // d 0-15
            ldsm2(kb2, kaddr + 32);   // d 16-31
            mma16816(s[nt], qa[0], kb);
            mma16816(s[nt], qa[1], kb2);
        }
        // bias + mask
#pragma unroll
        for (int nt = 0; nt < 8; nt++) {
            int kloc = nt * 8 + qp;
            float2 b0 = *(const float2*)(bpr0 + c * 64 + kloc);
            float2 b1 = *(const float2*)(bpr1 + c * 64 + kloc);
            s[nt][0] += b0.x + (((m0 >> kloc) & 1) ? -100.f : 0.f);
            s[nt][1] += b0.y + (((m0 >> (kloc + 1)) & 1) ? -100.f : 0.f);
            s[nt][2] += b1.x + (((m1 >> kloc) & 1) ? -100.f : 0.f);
            s[nt][3] += b1.y + (((m1 >> (kloc + 1)) & 1) ? -100.f : 0.f);
        }
        // online softmax on fragments (rows g, g+8; 4-lane quads)
        float mx0 = -1e30f, mx1 = -1e30f;
#pragma unroll
        for (int nt = 0; nt < 8; nt++) {
            mx0 = fmaxf(mx0, fmaxf(s[nt][0], s[nt][1]));
            mx1 = fmaxf(mx1, fmaxf(s[nt][2], s[nt][3]));
        }
        mx0 = fmaxf(mx0, __shfl_xor_sync(0xffffffffu, mx0, 1));
        mx0 = fmaxf(mx0, __shfl_xor_sync(0xffffffffu, mx0, 2));
        mx1 = fmaxf(mx1, __shfl_xor_sync(0xffffffffu, mx1, 1));
        mx1 = fmaxf(mx1, __shfl_xor_sync(0xffffffffu, mx1, 2));
        float mn0 = fmaxf(mi0, mx0), mn1 = fmaxf(mi1, mx1);
        uint32_t pa[8], pb[8];
        float l0 = 0.f, l1 = 0.f;
#pragma unroll
        for (int nt = 0; nt < 8; nt++) {
            float p0 = __expf(s[nt][0] - mn0), p1 = __expf(s[nt][1] - mn0);
            float p2 = __expf(s[nt][2] - mn1), p3 = __expf(s[nt][3] - mn1);
            l0 += p0 + p1; l1 += p2 + p3;
            __half2 h0 = __floats2half2_rn(p0, p1);
            __half2 h1 = __floats2half2_rn(p2, p3);
            pa[nt] = *(uint32_t*)&h0; pb[nt] = *(uint32_t*)&h1;
        }
        l0 += __shfl_xor_sync(0xffffffffu, l0, 1);
        l0 += __shfl_xor_sync(0xffffffffu, l0, 2);
        l1 += __shfl_xor_sync(0xffffffffu, l1, 1);
        l1 += __shfl_xor_sync(0xffffffffu, l1, 2);
        float sc0 = __expf(mi0 - mn0), sc1 = __expf(mi1 - mn1);
        li0 = li0 * sc0 + l0; li1 = li1 * sc1 + l1;
        mi0 = mn0; mi1 = mn1;
#pragma unroll
        for (int nt2 = 0; nt2 < 4; nt2++) {
            o[nt2][0] *= sc0; o[nt2][1] *= sc0;
            o[nt2][2] *= sc1; o[nt2][3] *= sc1;
        }
        // O += P V  (P fragments reused directly as A operands)
#pragma unroll
        for (int ks4 = 0; ks4 < 4; ks4++) {
            uint32_t af[4] = {pa[2 * ks4], pb[2 * ks4], pa[2 * ks4 + 1], pb[2 * ks4 + 1]};
#pragma unroll
            for (int nt2 = 0; nt2 < 4; nt2++) {
                uint32_t bv[2];
                bv[0] = *(const uint32_t*)((char*)vT + ((nt2 * 8 + g) * 72 + ks4 * 16 + qp) * 2);
                bv[1] = *(const uint32_t*)((char*)vT + ((nt2 * 8 + g) * 72 + ks4 * 16 + 8 + qp) * 2);
                mma16816(o[nt2], af, bv);
            }
        }
    }

    float inv0 = 1.f / li0, inv1 = 1.f / li1;
    int rn0 = rtile * 64 + wm + g;
    size_t base = ((size_t)b_ * NWIN + rn0) * CDIM + head * 32 + qp;
#pragma unroll
    for (int nt2 = 0; nt2 < 4; nt2++) {
        *(float2*)(g_a + base + nt2 * 8) = make_float2(o[nt2][0] * inv0, o[nt2][1] * inv0);
        *(float2*)(g_a + base + 8 * CDIM + nt2 * 8) = make_float2(o[nt2][2] * inv1, o[nt2][3] * inv1);
    }
}

// ---------------- launch ----------------
extern "C" void kernel_launch(void* const* d_in, const int* in_sizes, int n_in,
                              void* d_out, int out_size) {
    (void)in_sizes; (void)n_in; (void)out_size;
    const float* x      = (const float*)d_in[0];
    const float* ln1_g  = (const float*)d_in[1];
    const float* ln1_b  = (const float*)d_in[2];
    const float* qkv_w  = (const float*)d_in[3];
    const float* qkv_b  = (const float*)d_in[4];
    const float* table  = (const float*)d_in[5];
    const float* proj_w = (const float*)d_in[6];
    const float* proj_b = (const float*)d_in[7];
    const float* ln2_g  = (const float*)d_in[8];
    const float* ln2_b  = (const float*)d_in[9];
    const float* fc1_w  = (const float*)d_in[10];
    const float* fc1_b  = (const float*)d_in[11];
    const float* fc2_w  = (const float*)d_in[12];
    const float* fc2_b  = (const float*)d_in[13];
    float* out = (float*)d_out;

    cvt_all<<<(NWQ + NWP + NW1 + NW2 + 255) / 256, 256>>>(qkv_w, proj_w, fc1_w, fc2_w);
    bias_kernel<<<600, 1024>>>(table);
    ln_kernel<0><<<ROWS / 8, 256>>>(x, ln1_g, ln1_b);
    hgemm<1, 0, true,  EpiQKV ><<<dim3(9, 320),  256>>>(qkv_b, 192, EpiQKV{});
    attn_kernel<<<dim3(5, BH), 128>>>();
    hgemm<2, 1, false, EpiProj><<<dim3(3, 320),  256>>>(proj_b, 192, EpiProj{x});
    ln_kernel<1><<<ROWS / 8, 256>>>(nullptr, ln2_g, ln2_b);
    hgemm<1, 2, false, EpiGelu><<<dim3(12, 320), 256>>>(fc1_b, 192, EpiGelu{});
    hgemm<3, 3, false, EpiOut ><<<dim3(3, 320),  256>>>(fc2_b, 768, EpiOut{out});
}

// round 17
// speedup vs baseline: 1.2485x; 1.2485x over previous
#include <cuda_runtime.h>
#include <cuda_fp16.h>
#include <math.h>
#include <stdint.h>

// ---------------- problem constants ----------------
#define ROWS      40960
#define CDIM      192
#define NWIN      320
#define BH        768
#define MLPH      768
#define QK_SCALE  0.17677669529663687f

// ---------------- scratch ----------------
__device__ __half g_h [ (size_t)ROWS * CDIM ];        // LN out (fp16)
__device__ __half g_qh[ (size_t)BH * NWIN * 32 ];
__device__ __half g_kh[ (size_t)BH * NWIN * 32 ];
__device__ __half g_vh[ (size_t)BH * NWIN * 32 ];
__device__ __half g_a [ (size_t)ROWS * CDIM ];        // attn out (fp16)
__device__ float  g_x1[ (size_t)ROWS * CDIM ];        // attn residual (fp32)
__device__ __half g_g [ (size_t)ROWS * MLPH ];        // gelu out (fp16)
__device__ float  g_bias6[ 6 * NWIN * NWIN ];
// fp16 weights
__device__ __half g_wq[576 * 192];
__device__ __half g_wp[192 * 192];
__device__ __half g_w1[768 * 192];
__device__ __half g_w2[192 * 768];

__device__ __forceinline__ int winmap(int wr) {
    int b_ = wr / NWIN, n = wr - b_ * NWIN;
    int b  = b_ >> 6,  w = b_ & 63;
    int wh = w >> 3,   ww = w & 7;
    int t  = n >> 6;
    int rem = n & 63;
    int i = rem >> 3, j = rem & 7;
    int hs = (wh * 8 + i + 4) & 63;
    int ws = (ww * 8 + j + 4) & 63;
    return ((b * 5 + t) << 12) + (hs << 6) + ws;
}

// ---------------- mma / async helpers ----------------
__device__ __forceinline__ uint32_t smem_u32(const void* p) {
    uint32_t a;
    asm("{ .reg .u64 t; cvta.to.shared.u64 t, %1; cvt.u32.u64 %0, t; }" : "=r"(a) : "l"(p));
    return a;
}
__device__ __forceinline__ void ldsm4(uint32_t* r, uint32_t a) {
    asm volatile("ldmatrix.sync.aligned.m8n8.x4.shared.b16 {%0,%1,%2,%3}, [%4];"
        : "=r"(r[0]), "=r"(r[1]), "=r"(r[2]), "=r"(r[3]) : "r"(a));
}
__device__ __forceinline__ void ldsm2(uint32_t* r, uint32_t a) {
    asm volatile("ldmatrix.sync.aligned.m8n8.x2.shared.b16 {%0,%1}, [%2];"
        : "=r"(r[0]), "=r"(r[1]) : "r"(a));
}
__device__ __forceinline__ void mma16816(float* c, const uint32_t* a, const uint32_t* b) {
    asm volatile("mma.sync.aligned.m16n8k16.row.col.f32.f16.f16.f32 "
        "{%0,%1,%2,%3}, {%4,%5,%6,%7}, {%8,%9}, {%0,%1,%2,%3};"
        : "+f"(c[0]), "+f"(c[1]), "+f"(c[2]), "+f"(c[3])
        : "r"(a[0]), "r"(a[1]), "r"(a[2]), "r"(a[3]), "r"(b[0]), "r"(b[1]));
}
__device__ __forceinline__ void cp16(uint32_t dst, const void* src) {
    asm volatile("cp.async.cg.shared.global [%0], [%1], 16;" :: "r"(dst), "l"(src));
}
__device__ __forceinline__ void cp_commit() { asm volatile("cp.async.commit_group;"); }
__device__ __forceinline__ void cp_wait0() { asm volatile("cp.async.wait_group 0;"); }
__device__ __forceinline__ void cp_wait1() { asm volatile("cp.async.wait_group 1;"); }

// ---------------- merged weight fp16 conversion ----------------
#define NWQ (576*192)
#define NWP (192*192)
#define NW1 (768*192)
#define NW2 (192*768)
__global__ void cvt_all(const float* __restrict__ qkvw, const float* __restrict__ projw,
                        const float* __restrict__ f1w, const float* __restrict__ f2w) {
    int i = blockIdx.x * 256 + threadIdx.x;
    if (i < NWQ) g_wq[i] = __float2half(qkvw[i]);
    else if (i < NWQ + NWP) g_wp[i - NWQ] = __float2half(projw[i - NWQ]);
    else if (i < NWQ + NWP + NW1) g_w1[i - NWQ - NWP] = __float2half(f1w[i - NWQ - NWP]);
    else if (i < NWQ + NWP + NW1 + NW2) g_w2[i - NWQ - NWP - NW1] = __float2half(f2w[i - NWQ - NWP - NW1]);
}

// ---------------- relative-position bias precompute ----------------
__global__ void bias_kernel(const float* __restrict__ table) {
    int e = blockIdx.x * 1024 + threadIdx.x;
    if (e >= 6 * NWIN * NWIN) return;
    int head = e / (NWIN * NWIN);
    int r = e - head * (NWIN * NWIN);
    int n = r / NWIN, m = r - n * NWIN;
    int t1 = n >> 6, p1 = n & 63, i1 = p1 >> 3, j1 = p1 & 7;
    int t2 = m >> 6, p2 = m & 63, i2 = p2 >> 3, j2 = p2 & 7;
    int idx = (t1 - t2 + 7) * 15 + (i1 - i2 + 7) + (j1 - j2);
    g_bias6[e] = table[idx * 6 + head];
}

// ---------------- LayerNorm (fp32 in -> fp16 out) ----------------
template<int SRC>
__global__ __launch_bounds__(256) void ln_kernel(const float* __restrict__ in,
                                                 const float* __restrict__ gw,
                                                 const float* __restrict__ bw) {
    int row  = blockIdx.x * 8 + (threadIdx.x >> 5);
    int lane = threadIdx.x & 31;
    const float* src = (SRC == 0) ? in : g_x1;
    const float* p = src + (size_t)row * CDIM;
    float v[6];
    float s = 0.f;
#pragma unroll
    for (int u = 0; u < 3; u++) {
        float2 f = *(const float2*)(p + u * 64 + lane * 2);
        v[2 * u] = f.x; v[2 * u + 1] = f.y;
        s += f.x + f.y;
    }
#pragma unroll
    for (int o = 16; o; o >>= 1) s += __shfl_xor_sync(0xffffffffu, s, o);
    float mu = s * (1.0f / CDIM);
    float q = 0.f;
#pragma unroll
    for (int u = 0; u < 6; u++) { float d = v[u] - mu; q += d * d; }
#pragma unroll
    for (int o = 16; o; o >>= 1) q += __shfl_xor_sync(0xffffffffu, q, o);
    float rs = rsqrtf(q * (1.0f / CDIM) + 1e-5f);
    __half* o = g_h + (size_t)row * CDIM;
#pragma unroll
    for (int u = 0; u < 3; u++) {
        int c = u * 64 + lane * 2;
        float2 gb = *(const float2*)(gw + c);
        float2 bb = *(const float2*)(bw + c);
        *(__half2*)(o + c) = __floats2half2_rn((v[2*u] - mu) * rs * gb.x + bb.x,
                                               (v[2*u+1] - mu) * rs * gb.y + bb.y);
    }
}

// ---------------- GEMM epilogues ----------------
struct EpiQKV {
    __device__ void operator()(int wr, int oc, float val) const {
        int which = oc / CDIM;
        int rem = oc - which * CDIM;
        int h = rem >> 5, d = rem & 31;
        int b_ = wr / NWIN, n = wr - b_ * NWIN;
        size_t off = ((size_t)(b_ * 6 + h)) * (NWIN * 32) + (size_t)n * 32 + d;
        if (which == 0)      g_qh[off] = __float2half(val * QK_SCALE);
        else if (which == 1) g_kh[off] = __float2half(val);
        else                 g_vh[off] = __float2half(val);
    }
};
struct EpiProj {
    const float* x;
    __device__ void operator()(int wr, int c, float v) const {
        int dst = winmap(wr);
        size_t o = (size_t)dst * CDIM + c;
        g_x1[o] = x[o] + v;
    }
};
struct EpiGelu {
    __device__ void operator()(int r, int c, float v) const {
        g_g[(size_t)r * MLPH + c] = __float2half(0.5f * v * (1.0f + erff(v * 0.7071067811865476f)));
    }
};
struct EpiOut {
    float* out;
    __device__ void operator()(int r, int c, float v) const {
        size_t o = (size_t)r * CDIM + c;
        out[o] = g_x1[o] + v;
    }
};

// ---------------- HMMA GEMM: 128(M) x 64(N), K chunks 64, cp.async dbl-buffer ----
// A fp16 in gmem. smem rows 64 halves = 128B, XOR-swizzled 16B units by row%8.
template<int ASRC, int WSRC, bool GATHER, class Epi>
__global__ __launch_bounds__(256) void hgemm(const float* __restrict__ bias, int K, Epi epi) {
    __shared__ __align__(128) __half sA[2][128 * 64];
    __shared__ __align__(128) __half sW[2][64 * 64];
    const __half* Asrc = (ASRC == 1) ? g_h : (ASRC == 2) ? g_a : g_g;
    const __half* Wb = (WSRC == 0) ? g_wq : (WSRC == 1) ? g_wp : (WSRC == 2) ? g_w1 : g_w2;

    int tid = threadIdx.x, lane = tid & 31, warp = tid >> 5;
    int bm = blockIdx.y, bn = blockIdx.x;
    int wm = (warp & 3) * 32, wn = (warp >> 2) * 32;
    uint32_t sAb = smem_u32(sA), sWb = smem_u32(sW);

    int lrow = tid >> 3;                       // 0..31
    int cb   = ((tid & 7) * 16) ^ ((lrow & 7) << 4);   // swizzled byte col
    int kq   = (tid & 7) * 8;                  // halves

    const __half* Aptr[4];
#pragma unroll
    for (int i = 0; i < 4; i++) {
        int grow = bm * 128 + lrow + i * 32;
        int as = GATHER ? winmap(grow) : grow;
        Aptr[i] = Asrc + (size_t)as * K + kq;
    }
    const __half* Wptr[2];
#pragma unroll
    for (int i = 0; i < 2; i++)
        Wptr[i] = Wb + (size_t)(bn * 64 + lrow + i * 32) * K + kq;

    int aq = lane >> 3, ar = lane & 7;
    int a_row0 = wm + ar + (aq & 1) * 8;
    int a_cbase = (aq >> 1) * 16;
    int bl = lane & 15;
    int b_row0 = wn + (bl & 7);
    int b_cbase = ((bl >> 3) & 1) * 16;

    float acc[2][4][4];
#pragma unroll
    for (int mt = 0; mt < 2; mt++)
#pragma unroll
        for (int nt = 0; nt < 4; nt++)
#pragma unroll
            for (int e = 0; e < 4; e++) acc[mt][nt][e] = 0.f;

    int nch = K >> 6;
    // issue chunk 0 into buf 0
    {
#pragma unroll
        for (int i = 0; i < 4; i++)
            cp16(sAb + (uint32_t)((lrow + i * 32) * 128 + cb), Aptr[i]);
#pragma unroll
        for (int i = 0; i < 2; i++)
            cp16(sWb + (uint32_t)((lrow + i * 32) * 128 + cb), Wptr[i]);
        cp_commit();
    }

    for (int ch = 0; ch < nch; ch++) {
        int buf = ch & 1;
        if (ch + 1 < nch) {
            int nb = buf ^ 1;
            int k0 = (ch + 1) * 64;
#pragma unroll
            for (int i = 0; i < 4; i++)
                cp16(sAb + (uint32_t)(nb * 16384 + (lrow + i * 32) * 128 + cb), Aptr[i] + k0);
#pragma unroll
            for (int i = 0; i < 2; i++)
                cp16(sWb + (uint32_t)(nb * 8192 + (lrow + i * 32) * 128 + cb), Wptr[i] + k0);
            cp_commit();
            cp_wait1();
        } else {
            cp_wait0();
        }
        __syncthreads();

        uint32_t sAc = sAb + buf * 16384;
        uint32_t sWc = sWb + buf * 8192;
#pragma unroll
        for (int ks = 0; ks < 4; ks++) {
            int kb = ks * 32;
            uint32_t afr[2][4];
#pragma unroll
            for (int mt = 0; mt < 2; mt++) {
                int row = a_row0 + mt * 16;
                int c2 = (kb + a_cbase) ^ ((row & 7) << 4);
                ldsm4(afr[mt], sAc + row * 128 + c2);
            }
            uint32_t bfr[4][2];
#pragma unroll
            for (int nt = 0; nt < 4; nt++) {
                int row = b_row0 + nt * 8;
                int c2 = (kb + b_cbase) ^ ((row & 7) << 4);
                ldsm2(bfr[nt], sWc + row * 128 + c2);
            }
#pragma unroll
            for (int mt = 0; mt < 2; mt++)
#pragma unroll
                for (int nt = 0; nt < 4; nt++)
                    mma16816(acc[mt][nt], afr[mt], bfr[nt]);
        }
        __syncthreads();
    }

    int g = lane >> 2, cp = (lane & 3) * 2;
#pragma unroll
    for (int mt = 0; mt < 2; mt++) {
        int r0 = bm * 128 + wm + mt * 16 + g;
#pragma unroll
        for (int nt = 0; nt < 4; nt++) {
            int c0 = bn * 64 + wn + nt * 8 + cp;
            float b0 = bias[c0], b1 = bias[c0 + 1];
            epi(r0,     c0,     acc[mt][nt][0] + b0);
            epi(r0,     c0 + 1, acc[mt][nt][1] + b1);
            epi(r0 + 8, c0,     acc[mt][nt][2] + b0);
            epi(r0 + 8, c0 + 1, acc[mt][nt][3] + b1);
        }
    }
}

// ---------------- HMMA flash attention ----------------
// grid (5, 768), 128 threads (4 warps); warp w owns q rows [rtile*64+w*16, +16).
__global__ __launch_bounds__(128) void attn_kernel() {
    __shared__ __half qs[64 * 40];   // [row][d] rows 80B
    __shared__ __half ks[64 * 40];   // [key][d] (current chunk)
    __shared__ __half vT[32 * 72];   // [d][key] rows 144B
    __shared__ int    lab[64];

    int rtile = blockIdx.x, bh = blockIdx.y;
    int b_ = bh / 6, head = bh - b_ * 6;
    int tid = threadIdx.x, lane = tid & 31, warp = tid >> 5;
    int row6 = tid & 63, dhh = tid >> 6;

    {
        const __half* qg = g_qh + ((size_t)bh * NWIN + rtile * 64 + row6) * 32 + dhh * 16;
        uint4 q0 = *(const uint4*)qg;
        uint4 q1 = *(const uint4*)(qg + 8);
        *(uint4*)((char*)qs + row6 * 80 + dhh * 32) = q0;
        *(uint4*)((char*)qs + row6 * 80 + dhh * 32 + 16) = q1;
    }
    if (tid < 64) {
        int w = b_ & 63;
        int wh = w >> 3, ww = w & 7;
        int i = tid >> 3, j = tid & 7;
        int hh = wh * 8 + i, wg = ww * 8 + j;
        int lh = hh < 56 ? 0 : (hh < 60 ? 1 : 2);
        int lw = wg < 56 ? 0 : (wg < 60 ? 1 : 2);
        lab[tid] = lh * 3 + lw;
    }
    const __half* kg = g_kh + ((size_t)bh * NWIN + row6) * 32 + dhh * 16;
    const __half* vg = g_vh + ((size_t)bh * NWIN + row6) * 32 + dhh * 16;
    uint4 ka0 = *(const uint4*)kg, ka1 = *(const uint4*)(kg + 8);
    uint4 va0 = *(const uint4*)vg, va1 = *(const uint4*)(vg + 8);

    __syncthreads();

    int wm = warp * 16, g = lane >> 2, qp = (lane & 3) * 2;
    uint32_t qa[2][4];
    {
        int ar = lane & 7, aq = lane >> 3;
        uint32_t base = smem_u32(qs) + (uint32_t)((wm + ar + (aq & 1) * 8) * 80 + (aq >> 1) * 16);
        ldsm4(qa[0], base);
        ldsm4(qa[1], base + 32);
    }
    int labr0 = lab[wm + g], labr1 = lab[wm + g + 8];
    uint64_t m0 = 0, m1 = 0;
    for (int k2 = 0; k2 < 64; k2++) {
        int lk = lab[k2];
        m0 |= (uint64_t)(lk != labr0) << k2;
        m1 |= (uint64_t)(lk != labr1) << k2;
    }

    float mi0 = -1e30f, mi1 = -1e30f, li0 = 0.f, li1 = 0.f;
    float o[4][4] = {};
    const float* bpr0 = g_bias6 + (size_t)head * (NWIN * NWIN) + (size_t)(rtile * 64 + wm + g) * NWIN;
    const float* bpr1 = bpr0 + 8 * NWIN;
    uint32_t ksb = smem_u32(ks);
    int bl = lane & 15;

    for (int c = 0; c < 5; c++) {
        __syncthreads();
        *(uint4*)((char*)ks + row6 * 80 + dhh * 32) = ka0;
        *(uint4*)((char*)ks + row6 * 80 + dhh * 32 + 16) = ka1;
        {
            __half vh[16];
            *(uint4*)&vh[0] = va0; *(uint4*)&vh[8] = va1;
#pragma unroll
            for (int j = 0; j < 16; j++)
                vT[(dhh * 16 + j) * 72 + row6] = vh[j];
        }
        if (c < 4) {
            kg += 64 * 32; vg += 64 * 32;
            ka0 = *(const uint4*)kg; ka1 = *(const uint4*)(kg + 8);
            va0 = *(const uint4*)vg; va1 = *(const uint4*)(vg + 8);
        }
        __syncthreads();

        float s[8][4];
#pragma unroll
        for (int nt = 0; nt < 8; nt++) {
            s[nt][0] = s[nt][1] = s[nt][2] = s[nt][3] = 0.f;
            uint32_t kaddr = ksb + (uint32_t)((nt * 8 + (bl & 7)) * 80 + ((bl >> 3) & 1) * 16);
            uint32_t kb[2], kb2[2];
            ldsm2(kb,  kaddr);
            ldsm2(kb2, kaddr + 32);
            mma16816(s[nt], qa[0], kb);
            mma16816(s[nt], qa[1], kb2);
        }
#pragma unroll
        for (int nt = 0; nt < 8; nt++) {
            int kloc = nt * 8 + qp;
            float2 b0 = *(const float2*)(bpr0 + c * 64 + kloc);
            float2 b1 = *(const float2*)(bpr1 + c * 64 + kloc);
            s[nt][0] += b0.x + (((m0 >> kloc) & 1) ? -100.f : 0.f);
            s[nt][1] += b0.y + (((m0 >> (kloc + 1)) & 1) ? -100.f : 0.f);
            s[nt][2] += b1.x + (((m1 >> kloc) & 1) ? -100.f : 0.f);
            s[nt][3] += b1.y + (((m1 >> (kloc + 1)) & 1) ? -100.f : 0.f);
        }
        float mx0 = -1e30f, mx1 = -1e30f;
#pragma unroll
        for (int nt = 0; nt < 8; nt++) {
            mx0 = fmaxf(mx0, fmaxf(s[nt][0], s[nt][1]));
            mx1 = fmaxf(mx1, fmaxf(s[nt][2], s[nt][3]));
        }
        mx0 = fmaxf(mx0, __shfl_xor_sync(0xffffffffu, mx0, 1));
        mx0 = fmaxf(mx0, __shfl_xor_sync(0xffffffffu, mx0, 2));
        mx1 = fmaxf(mx1, __shfl_xor_sync(0xffffffffu, mx1, 1));
        mx1 = fmaxf(mx1, __shfl_xor_sync(0xffffffffu, mx1, 2));
        float mn0 = fmaxf(mi0, mx0), mn1 = fmaxf(mi1, mx1);
        uint32_t pa[8], pb[8];
        float l0 = 0.f, l1 = 0.f;
#pragma unroll
        for (int nt = 0; nt < 8; nt++) {
            float p0 = __expf(s[nt][0] - mn0), p1 = __expf(s[nt][1] - mn0);
            float p2 = __expf(s[nt][2] - mn1), p3 = __expf(s[nt][3] - mn1);
            l0 += p0 + p1; l1 += p2 + p3;
            __half2 h0 = __floats2half2_rn(p0, p1);
            __half2 h1 = __floats2half2_rn(p2, p3);
            pa[nt] = *(uint32_t*)&h0; pb[nt] = *(uint32_t*)&h1;
        }
        l0 += __shfl_xor_sync(0xffffffffu, l0, 1);
        l0 += __shfl_xor_sync(0xffffffffu, l0, 2);
        l1 += __shfl_xor_sync(0xffffffffu, l1, 1);
        l1 += __shfl_xor_sync(0xffffffffu, l1, 2);
        float sc0 = __expf(mi0 - mn0), sc1 = __expf(mi1 - mn1);
        li0 = li0 * sc0 + l0; li1 = li1 * sc1 + l1;
        mi0 = mn0; mi1 = mn1;
#pragma unroll
        for (int nt2 = 0; nt2 < 4; nt2++) {
            o[nt2][0] *= sc0; o[nt2][1] *= sc0;
            o[nt2][2] *= sc1; o[nt2][3] *= sc1;
        }
#pragma unroll
        for (int ks4 = 0; ks4 < 4; ks4++) {
            uint32_t af[4] = {pa[2 * ks4], pb[2 * ks4], pa[2 * ks4 + 1], pb[2 * ks4 + 1]};
#pragma unroll
            for (int nt2 = 0; nt2 < 4; nt2++) {
                uint32_t bv[2];
                bv[0] = *(const uint32_t*)((char*)vT + ((nt2 * 8 + g) * 72 + ks4 * 16 + qp) * 2);
                bv[1] = *(const uint32_t*)((char*)vT + ((nt2 * 8 + g) * 72 + ks4 * 16 + 8 + qp) * 2);
                mma16816(o[nt2], af, bv);
            }
        }
    }

    float inv0 = 1.f / li0, inv1 = 1.f / li1;
    int rn0 = rtile * 64 + wm + g;
    size_t base = ((size_t)b_ * NWIN + rn0) * CDIM + head * 32 + qp;
#pragma unroll
    for (int nt2 = 0; nt2 < 4; nt2++) {
        *(__half2*)(g_a + base + nt2 * 8) = __floats2half2_rn(o[nt2][0] * inv0, o[nt2][1] * inv0);
        *(__half2*)(g_a + base + 8 * CDIM + nt2 * 8) = __floats2half2_rn(o[nt2][2] * inv1, o[nt2][3] * inv1);
    }
}

// ---------------- launch ----------------
extern "C" void kernel_launch(void* const* d_in, const int* in_sizes, int n_in,
                              void* d_out, int out_size) {
    (void)in_sizes; (void)n_in; (void)out_size;
    const float* x      = (const float*)d_in[0];
    const float* ln1_g  = (const float*)d_in[1];
    const float* ln1_b  = (const float*)d_in[2];
    const float* qkv_w  = (const float*)d_in[3];
    const float* qkv_b  = (const float*)d_in[4];
    const float* table  = (const float*)d_in[5];
    const float* proj_w = (const float*)d_in[6];
    const float* proj_b = (const float*)d_in[7];
    const float* ln2_g  = (const float*)d_in[8];
    const float* ln2_b  = (const float*)d_in[9];
    const float* fc1_w  = (const float*)d_in[10];
    const float* fc1_b  = (const float*)d_in[11];
    const float* fc2_w  = (const float*)d_in[12];
    const float* fc2_b  = (const float*)d_in[13];
    float* out = (float*)d_out;

    cvt_all<<<(NWQ + NWP + NW1 + NW2 + 255) / 256, 256>>>(qkv_w, proj_w, fc1_w, fc2_w);
    bias_kernel<<<600, 1024>>>(table);
    ln_kernel<0><<<ROWS / 8, 256>>>(x, ln1_g, ln1_b);
    hgemm<1, 0, true,  EpiQKV ><<<dim3(9, 320),  256>>>(qkv_b, 192, EpiQKV{});
    attn_kernel<<<dim3(5, BH), 128>>>();
    hgemm<2, 1, false, EpiProj><<<dim3(3, 320),  256>>>(proj_b, 192, EpiProj{x});
    ln_kernel<1><<<ROWS / 8, 256>>>(nullptr, ln2_g, ln2_b);
    hgemm<1, 2, false, EpiGelu><<<dim3(12, 320), 256>>>(fc1_b, 192, EpiGelu{});
    hgemm<3, 3, false, EpiOut ><<<dim3(3, 320),  256>>>(fc2_b, 768, EpiOut{out});
}